// round 5
// baseline (speedup 1.0000x reference)
#include <cuda_runtime.h>
#include <cuda_bf16.h>

// BWSGODE: 8192-step serial Euler recurrence on 4 scalars.
//
// Serial chain -> bound by single-warp fma-pipe issue (rt_SMSP=2 on B300).
// Optimizations (all bit-exact vs the JAX reference's association order):
//  1. mask phase-split: generic scalar loop while mask can be 0 (<= ~4 iters
//     for i~U[0,1)), then a mask==1 specialized loop (x*1.0 == x bitwise).
//  2. packed f32x2 math in the hot loop: state as (B,W),(S,G) pairs; subs
//     become adds of pre-negated terms (a-b == a+(-b), (-p)*x == -(p*x));
//     identity lanes use +(-0.0f) and *1.0f (bitwise identities).
//  3. one STS.128 per iteration via a shared-space 32-bit address
//     (__cvta_generic_to_shared -> "r" operand), unroll-4 + 32-bit bump.
//  4. i-column filled by the idle threads concurrently with the serial loop;
//     coalesced scatter of cols 0-3 afterwards. 256 threads to halve the
//     parallel fill/scatter tails (serial loop unaffected).

#define NTHREADS 256

typedef unsigned long long u64;

#define MULX2(out, a, b) \
    asm("mul.rn.f32x2 %0, %1, %2;" : "=l"(out) : "l"(a), "l"(b))
#define ADDX2(out, a, b) \
    asm("add.rn.f32x2 %0, %1, %2;" : "=l"(out) : "l"(a), "l"(b))

static __device__ __forceinline__ u64 pk(float lo, float hi) {
    u64 r;
    asm("mov.b64 %0, {%1, %2};" : "=l"(r) : "f"(lo), "f"(hi));
    return r;
}
static __device__ __forceinline__ void upk(u64 v, float& lo, float& hi) {
    asm("mov.b64 {%0, %1}, %2;" : "=f"(lo), "=f"(hi) : "l"(v));
}

__global__ __launch_bounds__(NTHREADS, 1)
void bwsg_ode_kernel(const float* __restrict__ y0,
                     const float* __restrict__ params,
                     float* __restrict__ out,
                     int nsteps) {
    extern __shared__ float buf[];  // nsteps * 4 floats (B,W,S,G per row)

    const int tid = threadIdx.x;
    const float i_val = y0[4];

    // Fill the i-column in parallel; overlaps with the serial loop below.
    for (int r = tid; r < nsteps; r += NTHREADS) {
        out[r * 5 + 4] = i_val;
    }

    if (tid == 0) {
        float B = y0[0];
        float W = y0[1];
        float S = y0[2];
        float G = y0[3];

        const float p0 = params[0], p1 = params[1], p2 = params[2],
                    p3 = params[3], p4 = params[4], p5 = params[5],
                    p6 = params[6], p7 = params[7], p8 = params[8],
                    p9 = params[9];

        const bool interventional = (i_val != 0.0f);
        // threshold exactly as reference: (5.0 + i) - 1.0
        const float thr = __fsub_rn(__fadd_rn(5.0f, i_val), 1.0f);

        // First step index at which mask is guaranteed 1 from then on.
        int s_start = 1;
        if (interventional) {
            float c = ceilf(thr);
            if (c < 1.0f) c = 1.0f;
            if (c > (float)nsteps) c = (float)nsteps;
            s_start = (int)c;
        }

        buf[0] = B; buf[1] = W; buf[2] = S; buf[3] = G;

        // ---- Phase 1: generic (mask computed per step), few iterations ----
        for (int s = 1; s < s_start; ++s) {
            const float j    = (float)s;
            const float ge   = (j >= thr) ? 1.0f : 0.0f;
            const float mask = interventional ? ge : 1.0f;

            const float omG = __fsub_rn(1.0f, G);
            const float tG  = __fsub_rn(__fmul_rn(p0, omG), __fmul_rn(p1, S));
            const float dG  = __fmul_rn(tG, G);

            const float Bm = __fmul_rn(B, mask);

            const float uS = __fadd_rn(W, Bm);
            const float tS = __fsub_rn(
                __fsub_rn(__fmul_rn(p2, G), __fmul_rn(p3, uS)), p4);
            const float dS = __fmul_rn(S, tS);

            const float p6Bm = __fmul_rn(__fmul_rn(p6, B), mask);
            const float tW = __fsub_rn(__fsub_rn(__fmul_rn(p5, S), p6Bm), p7);
            const float dW = __fmul_rn(__fmul_rn(W, tW), W);

            const float uB = __fadd_rn(S, W);
            const float tB = __fsub_rn(__fmul_rn(p8, uB), p9);
            const float dB = __fmul_rn(Bm, tB);

            B = __fadd_rn(B, dB);
            W = __fadd_rn(W, dW);
            S = __fadd_rn(S, dS);
            G = __fadd_rn(G, dG);

            float* row = buf + s * 4;
            row[0] = B; row[1] = W; row[2] = S; row[3] = G;
        }

        // ---- Phase 2: mask == 1, packed f32x2 hot loop ----
        // Lane layout: BW = (B lo, W hi), SG = (S lo, G hi).
        u64 BW = pk(B, W);
        u64 SG = pk(S, G);

        const u64 cP20  = pk(p2, p0);           // (p2, p0)
        const u64 cN31  = pk(-p3, -p1);         // (-p3, -p1)
        const u64 cN4z  = pk(-p4, -0.0f);       // (-p4, -0)
        const u64 cP85  = pk(p8, p5);           // (p8, p5)
        const u64 cNzp7 = pk(-0.0f, -p7);       // (-0, -p7)
        const float np6 = __fmul_rn(p6, -1.0f); // exact negation
        const float np9 = __fmul_rn(p9, -1.0f);
        const float one = 1.0f;

        // 32-bit shared-space address for STS.128 (NOT a generic pointer).
        unsigned rowp = (unsigned)__cvta_generic_to_shared(buf + s_start * 4);

        #pragma unroll 4
        for (int s = s_start; s < nsteps; ++s) {
            // scalar cross-terms
            const float omG  = __fsub_rn(1.0f, G);
            const float uS   = __fadd_rn(W, B);      // W + B*1 == W + B
            const float uB   = __fadd_rn(S, W);
            const float p6Bn = __fmul_rn(np6, B);    // -(p6*B) exactly

            // (tS, tG) = ((p2*G - p3*uS) - p4, (p0*omG - p1*S) - 0)
            u64 m1; MULX2(m1, cP20, pk(G, omG));
            u64 m2; MULX2(m2, cN31, pk(uS, S));
            u64 t12; ADDX2(t12, m1, m2);
            ADDX2(t12, t12, cN4z);
            // (dS, dG) = (tS*S, tG*G)
            u64 d1; MULX2(d1, t12, SG);

            // (tB, tW) = ((p8*uB - p9) - 0, (p5*S - p6*B) - p7)
            u64 m3; MULX2(m3, cP85, pk(uB, S));
            u64 t34; ADDX2(t34, m3, pk(np9, p6Bn));
            ADDX2(t34, t34, cNzp7);
            // (dB, dW) = (B*tB * 1, W*tW * W)
            u64 d2; MULX2(d2, t34, BW);
            u64 d2b; MULX2(d2b, d2, pk(one, W));

            ADDX2(BW, BW, d2b);   // (B+dB, W+dW)
            ADDX2(SG, SG, d1);    // (S+dS, G+dG)

            // One STS.128: row = {B, W, S, G} (little-endian lanes).
            asm volatile("st.shared.v2.u64 [%0], {%1, %2};"
                         :: "r"(rowp), "l"(BW), "l"(SG) : "memory");
            rowp += 16;

            upk(BW, B, W);
            upk(SG, S, G);
        }
    }

    __syncthreads();

    // Coalesced scatter over the flat (nsteps,5) index space; col 4 was
    // already written during the serial loop.
    const int total = nsteps * 5;
    for (int idx = tid; idx < total; idx += NTHREADS) {
        const int r = idx / 5;
        const int c = idx - r * 5;
        if (c < 4) out[idx] = buf[r * 4 + c];
    }
}

extern "C" void kernel_launch(void* const* d_in, const int* in_sizes, int n_in,
                              void* d_out, int out_size) {
    const float* y0     = (const float*)d_in[0];
    const float* params = (const float*)d_in[1];
    float* out          = (float*)d_out;

    const int nsteps = out_size / 5;  // 8192
    const size_t smem = (size_t)nsteps * 4 * sizeof(float);  // 128 KB

    cudaFuncSetAttribute(bwsg_ode_kernel,
                         cudaFuncAttributeMaxDynamicSharedMemorySize,
                         (int)smem);

    bwsg_ode_kernel<<<1, NTHREADS, smem>>>(y0, params, out, nsteps);
}